// round 6
// baseline (speedup 1.0000x reference)
#include <cuda_runtime.h>
#include <stdint.h>

#define S   200
#define SS  40000
#define NB  16
#define P   256

// ---------------- device scratch (no dynamic allocation allowed) ----------------
__device__ float2 g_F [SS];        // DFT matrix exp(-2*pi*i*jk/200)
__device__ float2 g_PT[SS];        // phase_trig (amp * e^{i*phase})
__device__ float2 g_W [NB*SS];     // packed input waves
__device__ float2 g_T1[NB*SS];     // ping
__device__ float2 g_T2[NB*SS];     // pong

// ---------------- threefry2x32 (JAX-compatible, 20 rounds) ----------------
__host__ __device__ inline void tf2x32(uint32_t k0, uint32_t k1,
                                       uint32_t c0, uint32_t c1,
                                       uint32_t& o0, uint32_t& o1) {
    uint32_t ks2 = k0 ^ k1 ^ 0x1BD11BDAu;
    uint32_t x0 = c0 + k0, x1 = c1 + k1;
#define ROTL32(x,d) (((x)<<(d)) | ((x)>>(32-(d))))
#define RND(r) { x0 += x1; x1 = ROTL32(x1,(r)) ^ x0; }
    RND(13) RND(15) RND(26) RND(6)  x0 += k1;  x1 += ks2 + 1u;
    RND(17) RND(29) RND(16) RND(24) x0 += ks2; x1 += k0  + 2u;
    RND(13) RND(15) RND(26) RND(6)  x0 += k0;  x1 += k1  + 3u;
    RND(17) RND(29) RND(16) RND(24) x0 += k1;  x1 += ks2 + 4u;
    RND(13) RND(15) RND(26) RND(6)  x0 += ks2; x1 += k0  + 5u;
#undef RND
#undef ROTL32
    o0 = x0; o1 = x1;
}

// bits -> uniform(1e-10, 1.0) exactly as jax._src.random._uniform (no FMA fusion!)
__device__ inline float uniform_from_bits(uint32_t bits) {
    float f = __uint_as_float((bits >> 9) | 0x3f800000u) - 1.0f;  // [0,1)
    float u = f + 1e-10f;           // (1.0f - 1e-10f) == 1.0f in fp32
    return fmaxf(1e-10f, u);
}
__device__ inline float gumbel_precise(float u) { return -logf(-logf(u)); }
__device__ inline float gumbel_fast(float u)    { return -__logf(-__logf(u)); }

// orderable-uint mapping for floats (monotone), and inverse
__device__ inline uint32_t ford(float z) {
    uint32_t b = __float_as_uint(z);
    return (b & 0x80000000u) ? ~b : (b | 0x80000000u);
}
__device__ inline float funord(uint32_t ob) {
    uint32_t b = (ob & 0x80000000u) ? (ob ^ 0x80000000u) : ~ob;
    return __uint_as_float(b);
}

// ---------------- twiddle matrix ----------------
__global__ void k_twiddle() {
    int i = blockIdx.x * 256 + threadIdx.x;
    if (i >= SS) return;
    int j = i / S, k = i % S;
    int m = (j * k) % S;
    float sr, cr;
    sincospif((float)m / 100.0f, &sr, &cr);   // angle = 2*pi*jk/200
    g_F[i] = make_float2(cr, -sr);
}

// ---------------- pack waves ----------------
__global__ void k_pack(const float* __restrict__ wr, const float* __restrict__ wi) {
    int i = blockIdx.x * 256 + threadIdx.x;
    if (i < NB * SS) g_W[i] = make_float2(wr[i], wi[i]);
}

// ---------------- gumbel argmax (partitionable threefry) -> phase_trig ----------------
// one block per pixel; 256 threads = candidate index p
__global__ void __launch_bounds__(256)
k_phase(const float* __restrict__ volt,
        const float* __restrict__ pf,
        const float* __restrict__ itf,
        uint32_t k1a, uint32_t k1b, uint32_t k2a, uint32_t k2b) {
    int pix  = blockIdx.x;
    int p    = threadIdx.x;
    int warp = p >> 5, lane = p & 31;
    uint32_t j = (uint32_t)pix * 256u + (uint32_t)p;

    // partitionable random_bits: element j uses counter (hi=0, lo=j); bits = o0^o1
    uint32_t a0, a1, b0, b1;
    tf2x32(k1a, k1b, 0u, j, a0, a1);          // phase key
    tf2x32(k2a, k2b, 0u, j, b0, b1);          // intensity key
    float v = volt[j];

    __shared__ float              shf[8];
    __shared__ unsigned long long shp[8];
    __shared__ float              s_e[256];
    __shared__ int                s_res[2];

    float u_ch[2];
    u_ch[0] = uniform_from_bits(a0 ^ a1);
    u_ch[1] = uniform_from_bits(b0 ^ b1);

    for (int ch = 0; ch < 2; ch++) {
        float u  = u_ch[ch];
        // --- fast screen ---
        float za = (v + gumbel_fast(u)) * 0.1f;
        float m = za;
#pragma unroll
        for (int o = 16; o; o >>= 1) m = fmaxf(m, __shfl_xor_sync(0xffffffffu, m, o));
        if (lane == 0) shf[warp] = m;
        __syncthreads();
        float M = shf[0];
#pragma unroll
        for (int w = 1; w < 8; w++) M = fmaxf(M, shf[w]);
        __syncthreads();

        // --- precise score for candidates only (z = (v+g)/10 with IEEE div, as XLA) ---
        float z = -__int_as_float(0x7f800000);   // -inf
        bool cand = (za >= M - 1e-4f);
        if (cand) z = (v + gumbel_precise(u)) / 10.0f;

        unsigned long long key =
            ((unsigned long long)ford(z) << 32) | (unsigned long long)(255 - p);

        // --- top-1 (first-index on ties via 255-p packing) ---
        unsigned long long kv = key;
#pragma unroll
        for (int o = 16; o; o >>= 1) {
            unsigned long long other = __shfl_xor_sync(0xffffffffu, kv, o);
            if (other > kv) kv = other;
        }
        if (lane == 0) shp[warp] = kv;
        __syncthreads();
        unsigned long long K1 = shp[0];
#pragma unroll
        for (int w = 1; w < 8; w++) if (shp[w] > K1) K1 = shp[w];
        int   i1 = 255 - (int)(K1 & 0xffull);
        float z1 = funord((uint32_t)(K1 >> 32));
        __syncthreads();

        // --- top-2 (exclude i1) ---
        unsigned long long key2 = (p == i1) ? 0ull : key;
        kv = key2;
#pragma unroll
        for (int o = 16; o; o >>= 1) {
            unsigned long long other = __shfl_xor_sync(0xffffffffu, kv, o);
            if (other > kv) kv = other;
        }
        if (lane == 0) shp[warp] = kv;
        __syncthreads();
        unsigned long long K2 = shp[0];
#pragma unroll
        for (int w = 1; w < 8; w++) if (shp[w] > K2) K2 = shp[w];
        int   i2 = 255 - (int)(K2 & 0xffull);
        float z2 = funord((uint32_t)(K2 >> 32));
        __syncthreads();

        int result = i1;
        // --- rare danger branch: ulp-collapse in reference's softmax->argmax ---
        if (i2 < i1 && (z1 - z2) < 1.5e-7f) {
            float zd = cand ? z : za;           // approx ok for the common sum
            float e  = expf(zd - z1);
            s_e[p] = e;
            __syncthreads();
            for (int off = 128; off > 0; off >>= 1) {
                if (p < off) s_e[p] += s_e[p + off];
                __syncthreads();
            }
            float ssum = s_e[0];
            float y1 = 1.0f / ssum;             // exp(z1-z1)=1 exactly
            float y2 = expf(z2 - z1) / ssum;
            if (__float_as_uint(y1) == __float_as_uint(y2)) result = i2;
            __syncthreads();
        }
        if (p == 0) s_res[ch] = result;
        __syncthreads();
    }

    if (p == 0) {
        float ph = pf[s_res[0]];
        float am = itf[s_res[1]] * 6.0f;
        float sn, cs;
        sincosf(ph, &sn, &cs);
        g_PT[pix] = make_float2(am * cs, am * sn);
    }
}

// ---------------- complex 200x200x200 GEMM ----------------
// mode 0: T1 = F @ W          mode 1: T2 = (T1 @ F) .* h
// mode 2: T1 = conj(F) @ T2   mode 3: T2 = T1 @ conj(F)
#define BM 64
#define BN 64
#define BK 16
__global__ void k_zgemm(int mode, const float* __restrict__ hr, const float* __restrict__ hi) {
    const float2* A; const float2* Bm; float2* C;
    int   strideA = 0, strideB = 0;
    float sA = 1.0f, sB = 1.0f;
    bool  useH = false;
    switch (mode) {
        case 0: A = g_F;  Bm = g_W;  C = g_T1; strideB = SS; break;
        case 1: A = g_T1; Bm = g_F;  C = g_T2; strideA = SS; useH = true; break;
        case 2: A = g_F;  Bm = g_T2; C = g_T1; strideB = SS; sA = -1.0f;  break;
        default:A = g_T1; Bm = g_F;  C = g_T2; strideA = SS; sB = -1.0f;  break;
    }
    int b = blockIdx.z;
    A  += (size_t)b * strideA;
    Bm += (size_t)b * strideB;
    C  += (size_t)b * SS;

    __shared__ float2 As[BK][BM];
    __shared__ float2 Bs[BK][BN];

    int tid = threadIdx.x;
    int tx = tid & 15, ty = tid >> 4;
    int m0 = blockIdx.y * BM, n0 = blockIdx.x * BN;

    float2 acc[4][4];
#pragma unroll
    for (int i = 0; i < 4; i++)
#pragma unroll
        for (int j = 0; j < 4; j++) acc[i][j] = make_float2(0.f, 0.f);

    for (int k0 = 0; k0 < S; k0 += BK) {
#pragma unroll
        for (int l = 0; l < 4; l++) {
            int e = tid + 256 * l;
            int m = e >> 4, kk = e & 15;
            float2 v = make_float2(0.f, 0.f);
            if (m0 + m < S && k0 + kk < S) v = A[(m0 + m) * S + (k0 + kk)];
            v.y *= sA;
            As[kk][m] = v;
        }
#pragma unroll
        for (int l = 0; l < 4; l++) {
            int e = tid + 256 * l;
            int n = e & 63, kk = e >> 6;
            float2 v = make_float2(0.f, 0.f);
            if (k0 + kk < S && n0 + n < S) v = Bm[(k0 + kk) * S + (n0 + n)];
            v.y *= sB;
            Bs[kk][n] = v;
        }
        __syncthreads();
#pragma unroll
        for (int kk = 0; kk < BK; kk++) {
            float2 a[4], bb[4];
#pragma unroll
            for (int i = 0; i < 4; i++) a[i] = As[kk][ty * 4 + i];
#pragma unroll
            for (int j = 0; j < 4; j++) bb[j] = Bs[kk][tx * 4 + j];
#pragma unroll
            for (int i = 0; i < 4; i++)
#pragma unroll
                for (int j = 0; j < 4; j++) {
                    acc[i][j].x = fmaf(a[i].x,  bb[j].x, acc[i][j].x);
                    acc[i][j].x = fmaf(-a[i].y, bb[j].y, acc[i][j].x);
                    acc[i][j].y = fmaf(a[i].x,  bb[j].y, acc[i][j].y);
                    acc[i][j].y = fmaf(a[i].y,  bb[j].x, acc[i][j].y);
                }
        }
        __syncthreads();
    }
#pragma unroll
    for (int i = 0; i < 4; i++) {
        int m = m0 + ty * 4 + i;
        if (m >= S) continue;
#pragma unroll
        for (int j = 0; j < 4; j++) {
            int n = n0 + tx * 4 + j;
            if (n >= S) continue;
            float2 r = acc[i][j];
            if (useH) {
                float hx = hr[m * S + n], hy = hi[m * S + n];
                r = make_float2(r.x * hx - r.y * hy, r.x * hy + r.y * hx);
            }
            C[m * S + n] = r;
        }
    }
}

// ---------------- fused phase_trig multiply + pixel expansion ----------------
__global__ void k_expand(float* __restrict__ out) {
    int i = blockIdx.x, b = blockIdx.y;
    int tid = threadIdx.x;
    __shared__ float2 row[S];
    const float sc = 1.0f / (float)SS;
    for (int j = tid; j < S; j += 256) {
        float2 v  = g_T2[b * SS + i * S + j];
        float2 pt = g_PT[i * S + j];
        row[j] = make_float2((v.x * pt.x - v.y * pt.y) * sc,
                             (v.x * pt.y + v.y * pt.x) * sc);
    }
    __syncthreads();
    float4* obase = reinterpret_cast<float4*>(out) +
                    ((size_t)b * 2000 + (size_t)i * 10) * 1000;
    for (int di = 0; di < 10; di++) {
        float4* orow = obase + (size_t)di * 1000;
        if (di == 0 || di == 9) {
            for (int q = tid; q < 1000; q += 256) orow[q] = make_float4(0.f, 0.f, 0.f, 0.f);
        } else {
            for (int q = tid; q < 1000; q += 256) {
                int j  = q / 5;
                int k2 = q - j * 5;
                float2 v = row[j];
                float4 w;
                if      (k2 == 0) w = make_float4(0.f, 0.f, v.x, v.y);
                else if (k2 == 4) w = make_float4(v.x, v.y, 0.f, 0.f);
                else              w = make_float4(v.x, v.y, v.x, v.y);
                orow[q] = w;
            }
        }
    }
}

// ---------------- launch ----------------
extern "C" void kernel_launch(void* const* d_in, const int* in_sizes, int n_in,
                              void* d_out, int out_size) {
    const float* wr   = (const float*)d_in[0];
    const float* wi   = (const float*)d_in[1];
    const float* hr   = (const float*)d_in[2];
    const float* hi   = (const float*)d_in[3];
    const float* volt = (const float*)d_in[4];
    const float* pf   = (const float*)d_in[5];
    const float* itf  = (const float*)d_in[6];
    float* out = (float*)d_out;

    // jax.random.split(jax.random.key(42)) with threefry_partitionable=True:
    // new key i = full output pair of threefry(key, hi=0, lo=i)
    uint32_t k1a, k1b, k2a, k2b;
    tf2x32(0u, 42u, 0u, 0u, k1a, k1b);   // phase key     (keys[0])
    tf2x32(0u, 42u, 0u, 1u, k2a, k2b);   // intensity key (keys[1])

    k_twiddle<<<(SS + 255) / 256, 256>>>();
    k_pack<<<(NB * SS + 255) / 256, 256>>>(wr, wi);
    k_phase<<<SS, 256>>>(volt, pf, itf, k1a, k1b, k2a, k2b);

    dim3 gg((S + BN - 1) / BN, (S + BM - 1) / BM, NB);
    k_zgemm<<<gg, 256>>>(0, hr, hi);   // T1 = F @ W
    k_zgemm<<<gg, 256>>>(1, hr, hi);   // T2 = (T1 @ F) .* h
    k_zgemm<<<gg, 256>>>(2, hr, hi);   // T1 = conj(F) @ T2
    k_zgemm<<<gg, 256>>>(3, hr, hi);   // T2 = T1 @ conj(F)

    k_expand<<<dim3(S, NB), 256>>>(out);
}

// round 7
// speedup vs baseline: 1.3580x; 1.3580x over previous
#include <cuda_runtime.h>
#include <stdint.h>

#define S   200
#define SS  40000
#define NB  16
#define P   256

// ---------------- device scratch (no dynamic allocation allowed) ----------------
__device__ float2 g_F  [SS];       // DFT matrix exp(-2*pi*i*jk/200)
__device__ float2 g_PT [SS];       // phase_trig (amp * e^{i*phase})
__device__ float2 g_W  [NB*SS];    // packed input waves
__device__ float2 g_T1 [NB*SS];    // ping
__device__ float2 g_T2 [NB*SS];    // pong
__device__ float2 g_DaF[SS];       // D_a * F
__device__ float2 g_FDb[SS];       // F * D_b
__device__ float2 g_G1 [SS];       // (1/200) conj(F) D_a F
__device__ float2 g_G2 [SS];       // (1/200) F D_b conj(F)

// ---------------- threefry2x32 (JAX-compatible, 20 rounds) ----------------
__host__ __device__ inline void tf2x32(uint32_t k0, uint32_t k1,
                                       uint32_t c0, uint32_t c1,
                                       uint32_t& o0, uint32_t& o1) {
    uint32_t ks2 = k0 ^ k1 ^ 0x1BD11BDAu;
    uint32_t x0 = c0 + k0, x1 = c1 + k1;
#define ROTL32(x,d) (((x)<<(d)) | ((x)>>(32-(d))))
#define RND(r) { x0 += x1; x1 = ROTL32(x1,(r)) ^ x0; }
    RND(13) RND(15) RND(26) RND(6)  x0 += k1;  x1 += ks2 + 1u;
    RND(17) RND(29) RND(16) RND(24) x0 += ks2; x1 += k0  + 2u;
    RND(13) RND(15) RND(26) RND(6)  x0 += k0;  x1 += k1  + 3u;
    RND(17) RND(29) RND(16) RND(24) x0 += k1;  x1 += ks2 + 4u;
    RND(13) RND(15) RND(26) RND(6)  x0 += ks2; x1 += k0  + 5u;
#undef RND
#undef ROTL32
    o0 = x0; o1 = x1;
}

// bits -> uniform(1e-10, 1.0) exactly as jax._src.random._uniform (no FMA fusion!)
__device__ inline float uniform_from_bits(uint32_t bits) {
    float f = __uint_as_float((bits >> 9) | 0x3f800000u) - 1.0f;  // [0,1)
    float u = f + 1e-10f;
    return fmaxf(1e-10f, u);
}
__device__ inline float gumbel_precise(float u) { return -logf(-logf(u)); }
__device__ inline float gumbel_fast(float u)    { return -__logf(-__logf(u)); }

__device__ inline uint32_t ford(float z) {
    uint32_t b = __float_as_uint(z);
    return (b & 0x80000000u) ? ~b : (b | 0x80000000u);
}
__device__ inline float funord(uint32_t ob) {
    uint32_t b = (ob & 0x80000000u) ? (ob ^ 0x80000000u) : ~ob;
    return __uint_as_float(b);
}

// ---------------- twiddle matrix ----------------
__global__ void k_twiddle() {
    int i = blockIdx.x * 256 + threadIdx.x;
    if (i >= SS) return;
    int j = i / S, k = i % S;
    int m = (j * k) % S;
    float sr, cr;
    sincospif((float)m / 100.0f, &sr, &cr);
    g_F[i] = make_float2(cr, -sr);
}

// ---------------- pack waves ----------------
__global__ void k_pack(const float* __restrict__ wr, const float* __restrict__ wi) {
    int i = blockIdx.x * 256 + threadIdx.x;
    if (i < NB * SS) g_W[i] = make_float2(wr[i], wi[i]);
}

// ---------------- build D_a*F and F*D_b from separable h = a b^T ----------------
__global__ void k_build(const float* __restrict__ hr, const float* __restrict__ hi) {
    int i = blockIdx.x * 256 + threadIdx.x;
    if (i >= SS) return;
    int j = i / S, k = i % S;
    float2 F = g_F[i];
    // a_j = h[j,0]
    float2 a = make_float2(hr[j * S], hi[j * S]);
    // b_k = h[0,k] / h[0,0]
    float2 h0k = make_float2(hr[k], hi[k]);
    float2 h00 = make_float2(hr[0], hi[0]);
    float inv = 1.0f / (h00.x * h00.x + h00.y * h00.y);
    float2 b = make_float2((h0k.x * h00.x + h0k.y * h00.y) * inv,
                           (h0k.y * h00.x - h0k.x * h00.y) * inv);
    g_DaF[i] = make_float2(a.x * F.x - a.y * F.y, a.x * F.y + a.y * F.x);
    g_FDb[i] = make_float2(F.x * b.x - F.y * b.y, F.x * b.y + F.y * b.x);
}

// ---------------- gumbel argmax (partitionable threefry) -> phase_trig ----------------
__global__ void __launch_bounds__(256)
k_phase(const float* __restrict__ volt,
        const float* __restrict__ pf,
        const float* __restrict__ itf,
        uint32_t k1a, uint32_t k1b, uint32_t k2a, uint32_t k2b) {
    int pix  = blockIdx.x;
    int p    = threadIdx.x;
    int warp = p >> 5, lane = p & 31;
    uint32_t j = (uint32_t)pix * 256u + (uint32_t)p;

    uint32_t a0, a1, b0, b1;
    tf2x32(k1a, k1b, 0u, j, a0, a1);
    tf2x32(k2a, k2b, 0u, j, b0, b1);
    float v = volt[j];

    __shared__ float              shf[8];
    __shared__ unsigned long long shp[8];
    __shared__ float              s_e[256];
    __shared__ int                s_res[2];

    float u_ch[2];
    u_ch[0] = uniform_from_bits(a0 ^ a1);
    u_ch[1] = uniform_from_bits(b0 ^ b1);

    for (int ch = 0; ch < 2; ch++) {
        float u  = u_ch[ch];
        float za = (v + gumbel_fast(u)) * 0.1f;
        float m = za;
#pragma unroll
        for (int o = 16; o; o >>= 1) m = fmaxf(m, __shfl_xor_sync(0xffffffffu, m, o));
        if (lane == 0) shf[warp] = m;
        __syncthreads();
        float M = shf[0];
#pragma unroll
        for (int w = 1; w < 8; w++) M = fmaxf(M, shf[w]);
        __syncthreads();

        float z = -__int_as_float(0x7f800000);
        bool cand = (za >= M - 1e-4f);
        if (cand) z = (v + gumbel_precise(u)) / 10.0f;

        unsigned long long key =
            ((unsigned long long)ford(z) << 32) | (unsigned long long)(255 - p);

        unsigned long long kv = key;
#pragma unroll
        for (int o = 16; o; o >>= 1) {
            unsigned long long other = __shfl_xor_sync(0xffffffffu, kv, o);
            if (other > kv) kv = other;
        }
        if (lane == 0) shp[warp] = kv;
        __syncthreads();
        unsigned long long K1 = shp[0];
#pragma unroll
        for (int w = 1; w < 8; w++) if (shp[w] > K1) K1 = shp[w];
        int   i1 = 255 - (int)(K1 & 0xffull);
        float z1 = funord((uint32_t)(K1 >> 32));
        __syncthreads();

        unsigned long long key2 = (p == i1) ? 0ull : key;
        kv = key2;
#pragma unroll
        for (int o = 16; o; o >>= 1) {
            unsigned long long other = __shfl_xor_sync(0xffffffffu, kv, o);
            if (other > kv) kv = other;
        }
        if (lane == 0) shp[warp] = kv;
        __syncthreads();
        unsigned long long K2 = shp[0];
#pragma unroll
        for (int w = 1; w < 8; w++) if (shp[w] > K2) K2 = shp[w];
        int   i2 = 255 - (int)(K2 & 0xffull);
        float z2 = funord((uint32_t)(K2 >> 32));
        __syncthreads();

        int result = i1;
        if (i2 < i1 && (z1 - z2) < 1.5e-7f) {
            float zd = cand ? z : za;
            float e  = expf(zd - z1);
            s_e[p] = e;
            __syncthreads();
            for (int off = 128; off > 0; off >>= 1) {
                if (p < off) s_e[p] += s_e[p + off];
                __syncthreads();
            }
            float ssum = s_e[0];
            float y1 = 1.0f / ssum;
            float y2 = expf(z2 - z1) / ssum;
            if (__float_as_uint(y1) == __float_as_uint(y2)) result = i2;
            __syncthreads();
        }
        if (p == 0) s_res[ch] = result;
        __syncthreads();
    }

    if (p == 0) {
        float ph = pf[s_res[0]];
        float am = itf[s_res[1]] * 6.0f;
        float sn, cs;
        sincosf(ph, &sn, &cs);
        g_PT[pix] = make_float2(am * cs, am * sn);
    }
}

// ---------------- generic complex GEMM: C = scale * (cA?conj:id)(A) @ (cB?conj:id)(B) ----------------
// BM=64, BN=32, BK=16; 256 threads, micro-tile 4(m) x 2(n); float4 smem reads.
#define BM 64
#define BN 32
#define BK 16
#define APAD 66   // row stride of As in float2 (528B = 33*16B: float4-aligned, stores 2-way max)

__global__ void __launch_bounds__(256)
k_zgemm2(const float2* __restrict__ A, const float2* __restrict__ B, float2* __restrict__ C,
         int strideA, int strideB, int strideC,
         float cA, float cB, float scale) {
    int b = blockIdx.z;
    A += (size_t)b * strideA;
    B += (size_t)b * strideB;
    C += (size_t)b * strideC;

    __shared__ __align__(16) float2 As[BK][APAD];
    __shared__ __align__(16) float2 Bs[BK][BN];

    int tid = threadIdx.x;
    int tx = tid & 15;          // n-group: n = n0 + tx*2 + {0,1}
    int ty = tid >> 4;          // m-group: m = m0 + ty*4 + {0..3}
    int m0 = blockIdx.y * BM, n0 = blockIdx.x * BN;

    float2 acc[4][2];
#pragma unroll
    for (int i = 0; i < 4; i++)
#pragma unroll
        for (int j = 0; j < 2; j++) acc[i][j] = make_float2(0.f, 0.f);

    for (int k0 = 0; k0 < S; k0 += BK) {
        // A tile: 64 x 16 (consecutive threads read consecutive k -> coalesced)
#pragma unroll
        for (int l = 0; l < 4; l++) {
            int e = tid + 256 * l;
            int m = e >> 4, kk = e & 15;
            float2 v = make_float2(0.f, 0.f);
            if (m0 + m < S && k0 + kk < S) v = A[(m0 + m) * S + (k0 + kk)];
            v.y *= cA;
            As[kk][m] = v;
        }
        // B tile: 16 x 32
#pragma unroll
        for (int l = 0; l < 2; l++) {
            int e = tid + 256 * l;
            int n = e & 31, kk = e >> 5;
            float2 v = make_float2(0.f, 0.f);
            if (k0 + kk < S && n0 + n < S) v = B[(k0 + kk) * S + (n0 + n)];
            v.y *= cB;
            Bs[kk][n] = v;
        }
        __syncthreads();
#pragma unroll
        for (int kk = 0; kk < BK; kk++) {
            float4 bv  = *reinterpret_cast<const float4*>(&Bs[kk][tx * 2]);
            float4 a01 = *reinterpret_cast<const float4*>(&As[kk][ty * 4]);
            float4 a23 = *reinterpret_cast<const float4*>(&As[kk][ty * 4 + 2]);
            float2 a[4] = { make_float2(a01.x, a01.y), make_float2(a01.z, a01.w),
                            make_float2(a23.x, a23.y), make_float2(a23.z, a23.w) };
            float2 bb[2] = { make_float2(bv.x, bv.y), make_float2(bv.z, bv.w) };
#pragma unroll
            for (int i = 0; i < 4; i++)
#pragma unroll
                for (int j = 0; j < 2; j++) {
                    acc[i][j].x = fmaf(a[i].x,  bb[j].x, acc[i][j].x);
                    acc[i][j].x = fmaf(-a[i].y, bb[j].y, acc[i][j].x);
                    acc[i][j].y = fmaf(a[i].x,  bb[j].y, acc[i][j].y);
                    acc[i][j].y = fmaf(a[i].y,  bb[j].x, acc[i][j].y);
                }
        }
        __syncthreads();
    }
#pragma unroll
    for (int i = 0; i < 4; i++) {
        int m = m0 + ty * 4 + i;
        if (m >= S) continue;
#pragma unroll
        for (int j = 0; j < 2; j++) {
            int n = n0 + tx * 2 + j;
            if (n >= S) continue;
            C[m * S + n] = make_float2(acc[i][j].x * scale, acc[i][j].y * scale);
        }
    }
}

// ---------------- fused phase_trig multiply + pixel expansion ----------------
// (1/N^2 scale now absorbed into G1*G2)
__global__ void k_expand(float* __restrict__ out) {
    int i = blockIdx.x, b = blockIdx.y;
    int tid = threadIdx.x;
    __shared__ float2 row[S];
    for (int j = tid; j < S; j += 256) {
        float2 v  = g_T2[b * SS + i * S + j];
        float2 pt = g_PT[i * S + j];
        row[j] = make_float2(v.x * pt.x - v.y * pt.y,
                             v.x * pt.y + v.y * pt.x);
    }
    __syncthreads();
    float4* obase = reinterpret_cast<float4*>(out) +
                    ((size_t)b * 2000 + (size_t)i * 10) * 1000;
    for (int di = 0; di < 10; di++) {
        float4* orow = obase + (size_t)di * 1000;
        if (di == 0 || di == 9) {
            for (int q = tid; q < 1000; q += 256) orow[q] = make_float4(0.f, 0.f, 0.f, 0.f);
        } else {
            for (int q = tid; q < 1000; q += 256) {
                int j  = q / 5;
                int k2 = q - j * 5;
                float2 v = row[j];
                float4 w;
                if      (k2 == 0) w = make_float4(0.f, 0.f, v.x, v.y);
                else if (k2 == 4) w = make_float4(v.x, v.y, 0.f, 0.f);
                else              w = make_float4(v.x, v.y, v.x, v.y);
                orow[q] = w;
            }
        }
    }
}

// helper to fetch device-symbol addresses once (host side, graph-capturable: no allocs)
extern "C" void kernel_launch(void* const* d_in, const int* in_sizes, int n_in,
                              void* d_out, int out_size) {
    const float* wr   = (const float*)d_in[0];
    const float* wi   = (const float*)d_in[1];
    const float* hr   = (const float*)d_in[2];
    const float* hi   = (const float*)d_in[3];
    const float* volt = (const float*)d_in[4];
    const float* pf   = (const float*)d_in[5];
    const float* itf  = (const float*)d_in[6];
    float* out = (float*)d_out;

    static float2 *pF = nullptr, *pW, *pT1, *pT2, *pDaF, *pFDb, *pG1, *pG2;
    if (!pF) {
        cudaGetSymbolAddress((void**)&pF,   g_F);
        cudaGetSymbolAddress((void**)&pW,   g_W);
        cudaGetSymbolAddress((void**)&pT1,  g_T1);
        cudaGetSymbolAddress((void**)&pT2,  g_T2);
        cudaGetSymbolAddress((void**)&pDaF, g_DaF);
        cudaGetSymbolAddress((void**)&pFDb, g_FDb);
        cudaGetSymbolAddress((void**)&pG1,  g_G1);
        cudaGetSymbolAddress((void**)&pG2,  g_G2);
    }

    // jax.random.split(jax.random.key(42)), threefry_partitionable
    uint32_t k1a, k1b, k2a, k2b;
    tf2x32(0u, 42u, 0u, 0u, k1a, k1b);
    tf2x32(0u, 42u, 0u, 1u, k2a, k2b);

    k_twiddle<<<(SS + 255) / 256, 256>>>();
    k_pack<<<(NB * SS + 255) / 256, 256>>>(wr, wi);
    k_build<<<(SS + 255) / 256, 256>>>(hr, hi);
    k_phase<<<SS, 256>>>(volt, pf, itf, k1a, k1b, k2a, k2b);

    dim3 g1((S + BN - 1) / BN, (S + BM - 1) / BM, 1);    // 7 x 4
    dim3 gb((S + BN - 1) / BN, (S + BM - 1) / BM, NB);   // 7 x 4 x 16

    // G1 = (1/200) conj(F) @ (D_a F);  G2 = (1/200) (F D_b) @ conj(F)
    k_zgemm2<<<g1, 256>>>(pF,   pDaF, pG1, 0, 0, 0, -1.f,  1.f, 1.0f / 200.0f);
    k_zgemm2<<<g1, 256>>>(pFDb, pF,   pG2, 0, 0, 0,  1.f, -1.f, 1.0f / 200.0f);

    // per-batch: T1 = G1 @ W ; T2 = T1 @ G2
    k_zgemm2<<<gb, 256>>>(pG1, pW,  pT1, 0,  SS, SS, 1.f, 1.f, 1.0f);
    k_zgemm2<<<gb, 256>>>(pT1, pG2, pT2, SS, 0,  SS, 1.f, 1.f, 1.0f);

    k_expand<<<dim3(S, NB), 256>>>(out);
}

// round 11
// speedup vs baseline: 1.8138x; 1.3357x over previous
#include <cuda_runtime.h>
#include <stdint.h>

#define S   200
#define SS  40000
#define NB  16
#define P   256

// ---------------- device scratch (no dynamic allocation allowed) ----------------
__device__ float2 g_F  [SS];       // DFT matrix exp(-2*pi*i*jk/200)
__device__ float2 g_PT [SS];       // phase_trig (amp * e^{i*phase})
__device__ float2 g_W  [NB*SS];    // packed input waves
__device__ float2 g_T1 [NB*SS];    // ping
__device__ float2 g_T2 [NB*SS];    // pong
__device__ float2 g_DaF[SS];       // D_a * F
__device__ float2 g_FDb[SS];       // F * D_b
__device__ float2 g_G1 [SS];       // (1/200) conj(F) D_a F
__device__ float2 g_G2 [SS];       // (1/200) F D_b conj(F)

// ---------------- threefry2x32 (host/reference version) ----------------
__host__ __device__ inline void tf2x32(uint32_t k0, uint32_t k1,
                                       uint32_t c0, uint32_t c1,
                                       uint32_t& o0, uint32_t& o1) {
    uint32_t ks2 = k0 ^ k1 ^ 0x1BD11BDAu;
    uint32_t x0 = c0 + k0, x1 = c1 + k1;
#define ROTL32(x,d) (((x)<<(d)) | ((x)>>(32-(d))))
#define RND(r) { x0 += x1; x1 = ROTL32(x1,(r)) ^ x0; }
    RND(13) RND(15) RND(26) RND(6)  x0 += k1;  x1 += ks2 + 1u;
    RND(17) RND(29) RND(16) RND(24) x0 += ks2; x1 += k0  + 2u;
    RND(13) RND(15) RND(26) RND(6)  x0 += k0;  x1 += k1  + 3u;
    RND(17) RND(29) RND(16) RND(24) x0 += k1;  x1 += ks2 + 4u;
    RND(13) RND(15) RND(26) RND(6)  x0 += ks2; x1 += k0  + 5u;
#undef RND
#undef ROTL32
    o0 = x0; o1 = x1;
}

// pipe-balanced add: a + b via IMAD (fma pipe); `one` is a runtime reg => ptxas keeps IMAD
__device__ __forceinline__ uint32_t madd(uint32_t a, uint32_t b, uint32_t one) {
    uint32_t r;
    asm("mad.lo.u32 %0, %1, %2, %3;" : "=r"(r) : "r"(a), "r"(one), "r"(b));
    return r;
}

// device threefry, counter (0, j), returns o0^o1 (partitionable 32-bit random_bits)
__device__ __forceinline__ uint32_t tf_bits(uint32_t k0, uint32_t k1, uint32_t j, uint32_t one) {
    uint32_t ks2 = k0 ^ k1 ^ 0x1BD11BDAu;
    uint32_t i1b = ks2 + 1u, i2b = k0 + 2u, i3b = k1 + 3u, i4b = ks2 + 4u, i5b = k0 + 5u;
    uint32_t x0 = k0;                 // c0 = 0
    uint32_t x1 = madd(j, k1, one);   // c1 = j
#define RNDM(r) { x0 = madd(x0, x1, one); x1 = __funnelshift_l(x1, x1, (r)) ^ x0; }
    RNDM(13) RNDM(15) RNDM(26) RNDM(6)
    x0 = madd(x0, k1,  one); x1 = madd(x1, i1b, one);
    RNDM(17) RNDM(29) RNDM(16) RNDM(24)
    x0 = madd(x0, ks2, one); x1 = madd(x1, i2b, one);
    RNDM(13) RNDM(15) RNDM(26) RNDM(6)
    x0 = madd(x0, k0,  one); x1 = madd(x1, i3b, one);
    RNDM(17) RNDM(29) RNDM(16) RNDM(24)
    x0 = madd(x0, k1,  one); x1 = madd(x1, i4b, one);
    RNDM(13) RNDM(15) RNDM(26) RNDM(6)
    x0 = madd(x0, ks2, one); x1 = madd(x1, i5b, one);
#undef RNDM
    return x0 ^ x1;
}

// bits -> uniform(1e-10, 1.0) exactly as jax._src.random._uniform (no FMA fusion!)
__device__ inline float uniform_from_bits(uint32_t bits) {
    float f = __uint_as_float((bits >> 9) | 0x3f800000u) - 1.0f;  // [0,1)
    float u = f + 1e-10f;
    return fmaxf(1e-10f, u);
}
__device__ inline float gumbel_precise(float u) { return -logf(-logf(u)); }
__device__ inline float gumbel_fast(float u)    { return -__logf(-__logf(u)); }

__device__ inline uint32_t ford(float z) {
    uint32_t b = __float_as_uint(z);
    return (b & 0x80000000u) ? ~b : (b | 0x80000000u);
}
__device__ inline float funord(uint32_t ob) {
    uint32_t b = (ob & 0x80000000u) ? (ob ^ 0x80000000u) : ~ob;
    return __uint_as_float(b);
}

// ---------------- twiddle matrix ----------------
__global__ void k_twiddle() {
    int i = blockIdx.x * 256 + threadIdx.x;
    if (i >= SS) return;
    int j = i / S, k = i % S;
    int m = (j * k) % S;
    float sr, cr;
    sincospif((float)m / 100.0f, &sr, &cr);
    g_F[i] = make_float2(cr, -sr);
}

// ---------------- pack waves ----------------
__global__ void k_pack(const float* __restrict__ wr, const float* __restrict__ wi) {
    int i = blockIdx.x * 256 + threadIdx.x;
    if (i < NB * SS) g_W[i] = make_float2(wr[i], wi[i]);
}

// ---------------- build D_a*F and F*D_b from separable h = a b^T ----------------
__global__ void k_build(const float* __restrict__ hr, const float* __restrict__ hi) {
    int i = blockIdx.x * 256 + threadIdx.x;
    if (i >= SS) return;
    int j = i / S, k = i % S;
    float2 F = g_F[i];
    float2 a = make_float2(hr[j * S], hi[j * S]);
    float2 h0k = make_float2(hr[k], hi[k]);
    float2 h00 = make_float2(hr[0], hi[0]);
    float inv = 1.0f / (h00.x * h00.x + h00.y * h00.y);
    float2 b = make_float2((h0k.x * h00.x + h0k.y * h00.y) * inv,
                           (h0k.y * h00.x - h0k.x * h00.y) * inv);
    g_DaF[i] = make_float2(a.x * F.x - a.y * F.y, a.x * F.y + a.y * F.x);
    g_FDb[i] = make_float2(F.x * b.x - F.y * b.y, F.x * b.y + F.y * b.x);
}

// ---------------- gumbel argmax (partitionable threefry) -> phase_trig ----------------
// one block per pixel; 256 threads = candidate index p
__global__ void __launch_bounds__(256)
k_phase(const float* __restrict__ volt,
        const float* __restrict__ pf,
        const float* __restrict__ itf,
        uint32_t k1a, uint32_t k1b, uint32_t k2a, uint32_t k2b, uint32_t one) {
    int pix  = blockIdx.x;
    int p    = threadIdx.x;
    int warp = p >> 5, lane = p & 31;
    uint32_t j = (uint32_t)pix * 256u + (uint32_t)p;

    uint32_t bits0 = tf_bits(k1a, k1b, j, one);   // phase key
    uint32_t bits1 = tf_bits(k2a, k2b, j, one);   // intensity key
    float v  = volt[j];
    float u0 = uniform_from_bits(bits0);
    float u1 = uniform_from_bits(bits1);

    // fast screen scores (both channels)
    float za0 = (v + gumbel_fast(u0)) * 0.1f;
    float za1 = (v + gumbel_fast(u1)) * 0.1f;

    __shared__ float2 s_wm[8];
    __shared__ unsigned long long s_top[4];   // [0]=top1 ch0, [1]=top1 ch1, [2]=top2 ch0, [3]=top2 ch1
    __shared__ float s_e[256];
    __shared__ int   s_res[2];

    float m0 = za0, m1 = za1;
#pragma unroll
    for (int o = 16; o; o >>= 1) {
        m0 = fmaxf(m0, __shfl_xor_sync(0xffffffffu, m0, o));
        m1 = fmaxf(m1, __shfl_xor_sync(0xffffffffu, m1, o));
    }
    if (lane == 0) s_wm[warp] = make_float2(m0, m1);
    if (p == 0) { s_top[0] = 0ull; s_top[1] = 0ull; s_top[2] = 0ull; s_top[3] = 0ull; }
    __syncthreads();

    float M0 = s_wm[0].x, M1 = s_wm[0].y;
#pragma unroll
    for (int w = 1; w < 8; w++) {
        M0 = fmaxf(M0, s_wm[w].x);
        M1 = fmaxf(M1, s_wm[w].y);
    }

    // precise score for candidates only (z = (v+g)/10 with IEEE div, as XLA)
    bool c0 = (za0 >= M0 - 1e-4f);
    bool c1 = (za1 >= M1 - 1e-4f);
    float z0 = 0.f, z1 = 0.f;
    unsigned long long key0 = 0ull, key1 = 0ull;
    if (c0) {
        z0 = (v + gumbel_precise(u0)) / 10.0f;
        key0 = ((unsigned long long)ford(z0) << 32) | (unsigned long long)(255 - p);
        atomicMax(&s_top[0], key0);
    }
    if (c1) {
        z1 = (v + gumbel_precise(u1)) / 10.0f;
        key1 = ((unsigned long long)ford(z1) << 32) | (unsigned long long)(255 - p);
        atomicMax(&s_top[1], key1);
    }
    __syncthreads();

    int i1c0 = 255 - (int)(s_top[0] & 0xffull);
    int i1c1 = 255 - (int)(s_top[1] & 0xffull);
    if (c0 && p != i1c0) atomicMax(&s_top[2], key0);
    if (c1 && p != i1c1) atomicMax(&s_top[3], key1);
    __syncthreads();

    // per-channel final result with rare softmax ulp-collapse emulation
#pragma unroll
    for (int ch = 0; ch < 2; ch++) {
        unsigned long long K1 = s_top[ch];
        unsigned long long K2 = s_top[2 + ch];
        int   i1 = 255 - (int)(K1 & 0xffull);
        int   i2 = 255 - (int)(K2 & 0xffull);
        float zt1 = funord((uint32_t)(K1 >> 32));
        float zt2 = funord((uint32_t)(K2 >> 32));
        int result = i1;
        if (K2 != 0ull && i2 < i1 && (zt1 - zt2) < 1.5e-7f) {   // uniform across block
            bool  cc = (ch == 0) ? c0 : c1;
            float zc = (ch == 0) ? z0 : z1;
            float zf = (ch == 0) ? za0 : za1;
            float zd = cc ? zc : zf;
            s_e[p] = expf(zd - zt1);
            __syncthreads();
            for (int off = 128; off > 0; off >>= 1) {
                if (p < off) s_e[p] += s_e[p + off];
                __syncthreads();
            }
            float ssum = s_e[0];
            float y1 = 1.0f / ssum;                 // exp(z1-z1)=1 exactly
            float y2 = expf(zt2 - zt1) / ssum;
            if (__float_as_uint(y1) == __float_as_uint(y2)) result = i2;
            __syncthreads();
        }
        if (p == 0) s_res[ch] = result;
    }
    __syncthreads();

    if (p == 0) {
        float ph = pf[s_res[0]];
        float am = itf[s_res[1]] * 6.0f;
        float sn, cs;
        sincosf(ph, &sn, &cs);
        g_PT[pix] = make_float2(am * cs, am * sn);
    }
}

// ---------------- generic complex GEMM: C = scale * (cA?conj:id)(A) @ (cB?conj:id)(B) ----------------
#define BM 64
#define BN 32
#define BK 16
#define APAD 66   // row stride of As in float2 (528B = 33*16B: float4-aligned, stores 2-way max)

__global__ void __launch_bounds__(256)
k_zgemm2(const float2* __restrict__ A, const float2* __restrict__ B, float2* __restrict__ C,
         int strideA, int strideB, int strideC,
         float cA, float cB, float scale) {
    int b = blockIdx.z;
    A += (size_t)b * strideA;
    B += (size_t)b * strideB;
    C += (size_t)b * strideC;

    __shared__ __align__(16) float2 As[BK][APAD];
    __shared__ __align__(16) float2 Bs[BK][BN];

    int tid = threadIdx.x;
    int tx = tid & 15;
    int ty = tid >> 4;
    int m0 = blockIdx.y * BM, n0 = blockIdx.x * BN;

    float2 acc[4][2];
#pragma unroll
    for (int i = 0; i < 4; i++)
#pragma unroll
        for (int j = 0; j < 2; j++) acc[i][j] = make_float2(0.f, 0.f);

    for (int k0 = 0; k0 < S; k0 += BK) {
#pragma unroll
        for (int l = 0; l < 4; l++) {
            int e = tid + 256 * l;
            int m = e >> 4, kk = e & 15;
            float2 v = make_float2(0.f, 0.f);
            if (m0 + m < S && k0 + kk < S) v = A[(m0 + m) * S + (k0 + kk)];
            v.y *= cA;
            As[kk][m] = v;
        }
#pragma unroll
        for (int l = 0; l < 2; l++) {
            int e = tid + 256 * l;
            int n = e & 31, kk = e >> 5;
            float2 v = make_float2(0.f, 0.f);
            if (k0 + kk < S && n0 + n < S) v = B[(k0 + kk) * S + (n0 + n)];
            v.y *= cB;
            Bs[kk][n] = v;
        }
        __syncthreads();
#pragma unroll
        for (int kk = 0; kk < BK; kk++) {
            float4 bv  = *reinterpret_cast<const float4*>(&Bs[kk][tx * 2]);
            float4 a01 = *reinterpret_cast<const float4*>(&As[kk][ty * 4]);
            float4 a23 = *reinterpret_cast<const float4*>(&As[kk][ty * 4 + 2]);
            float2 a[4] = { make_float2(a01.x, a01.y), make_float2(a01.z, a01.w),
                            make_float2(a23.x, a23.y), make_float2(a23.z, a23.w) };
            float2 bb[2] = { make_float2(bv.x, bv.y), make_float2(bv.z, bv.w) };
#pragma unroll
            for (int i = 0; i < 4; i++)
#pragma unroll
                for (int j = 0; j < 2; j++) {
                    acc[i][j].x = fmaf(a[i].x,  bb[j].x, acc[i][j].x);
                    acc[i][j].x = fmaf(-a[i].y, bb[j].y, acc[i][j].x);
                    acc[i][j].y = fmaf(a[i].x,  bb[j].y, acc[i][j].y);
                    acc[i][j].y = fmaf(a[i].y,  bb[j].x, acc[i][j].y);
                }
        }
        __syncthreads();
    }
#pragma unroll
    for (int i = 0; i < 4; i++) {
        int m = m0 + ty * 4 + i;
        if (m >= S) continue;
#pragma unroll
        for (int j = 0; j < 2; j++) {
            int n = n0 + tx * 2 + j;
            if (n >= S) continue;
            C[m * S + n] = make_float2(acc[i][j].x * scale, acc[i][j].y * scale);
        }
    }
}

// ---------------- fused phase_trig multiply + pixel expansion ----------------
__global__ void k_expand(float* __restrict__ out) {
    int i = blockIdx.x, b = blockIdx.y;
    int tid = threadIdx.x;
    __shared__ float2 row[S];
    for (int j = tid; j < S; j += 256) {
        float2 v  = g_T2[b * SS + i * S + j];
        float2 pt = g_PT[i * S + j];
        row[j] = make_float2(v.x * pt.x - v.y * pt.y,
                             v.x * pt.y + v.y * pt.x);
    }
    __syncthreads();
    float4* obase = reinterpret_cast<float4*>(out) +
                    ((size_t)b * 2000 + (size_t)i * 10) * 1000;
    for (int di = 0; di < 10; di++) {
        float4* orow = obase + (size_t)di * 1000;
        if (di == 0 || di == 9) {
            for (int q = tid; q < 1000; q += 256) orow[q] = make_float4(0.f, 0.f, 0.f, 0.f);
        } else {
            for (int q = tid; q < 1000; q += 256) {
                int j  = q / 5;
                int k2 = q - j * 5;
                float2 v = row[j];
                float4 w;
                if      (k2 == 0) w = make_float4(0.f, 0.f, v.x, v.y);
                else if (k2 == 4) w = make_float4(v.x, v.y, 0.f, 0.f);
                else              w = make_float4(v.x, v.y, v.x, v.y);
                orow[q] = w;
            }
        }
    }
}

// ---------------- launch ----------------
extern "C" void kernel_launch(void* const* d_in, const int* in_sizes, int n_in,
                              void* d_out, int out_size) {
    const float* wr   = (const float*)d_in[0];
    const float* wi   = (const float*)d_in[1];
    const float* hr   = (const float*)d_in[2];
    const float* hi   = (const float*)d_in[3];
    const float* volt = (const float*)d_in[4];
    const float* pf   = (const float*)d_in[5];
    const float* itf  = (const float*)d_in[6];
    float* out = (float*)d_out;

    static float2 *pF = nullptr, *pW, *pT1, *pT2, *pDaF, *pFDb, *pG1, *pG2;
    if (!pF) {
        cudaGetSymbolAddress((void**)&pF,   g_F);
        cudaGetSymbolAddress((void**)&pW,   g_W);
        cudaGetSymbolAddress((void**)&pT1,  g_T1);
        cudaGetSymbolAddress((void**)&pT2,  g_T2);
        cudaGetSymbolAddress((void**)&pDaF, g_DaF);
        cudaGetSymbolAddress((void**)&pFDb, g_FDb);
        cudaGetSymbolAddress((void**)&pG1,  g_G1);
        cudaGetSymbolAddress((void**)&pG2,  g_G2);
    }

    // jax.random.split(jax.random.key(42)), threefry_partitionable
    uint32_t k1a, k1b, k2a, k2b;
    tf2x32(0u, 42u, 0u, 0u, k1a, k1b);
    tf2x32(0u, 42u, 0u, 1u, k2a, k2b);

    k_twiddle<<<(SS + 255) / 256, 256>>>();
    k_pack<<<(NB * SS + 255) / 256, 256>>>(wr, wi);
    k_build<<<(SS + 255) / 256, 256>>>(hr, hi);
    k_phase<<<SS, 256>>>(volt, pf, itf, k1a, k1b, k2a, k2b, 1u);

    dim3 g1((S + BN - 1) / BN, (S + BM - 1) / BM, 1);    // 7 x 4
    dim3 gb((S + BN - 1) / BN, (S + BM - 1) / BM, NB);   // 7 x 4 x 16

    // G1 = (1/200) conj(F) @ (D_a F);  G2 = (1/200) (F D_b) @ conj(F)
    k_zgemm2<<<g1, 256>>>(pF,   pDaF, pG1, 0, 0, 0, -1.f,  1.f, 1.0f / 200.0f);
    k_zgemm2<<<g1, 256>>>(pFDb, pF,   pG2, 0, 0, 0,  1.f, -1.f, 1.0f / 200.0f);

    // per-batch: T1 = G1 @ W ; T2 = T1 @ G2
    k_zgemm2<<<gb, 256>>>(pG1, pW,  pT1, 0,  SS, SS, 1.f, 1.f, 1.0f);
    k_zgemm2<<<gb, 256>>>(pT1, pG2, pT2, SS, 0,  SS, 1.f, 1.f, 1.0f);

    k_expand<<<dim3(S, NB), 256>>>(out);
}

// round 13
// speedup vs baseline: 1.8232x; 1.0052x over previous
#include <cuda_runtime.h>
#include <stdint.h>

#define S   200
#define SS  40000
#define NB  16
#define P   256
#define NGEMM 448          // 7 x 4 x 16 gemm tiles per fused launch
#define PHALF 20000        // phase pixels per fused launch

// ---------------- device scratch (no dynamic allocation allowed) ----------------
__device__ float2 g_F  [SS];       // DFT matrix exp(-2*pi*i*jk/200)
__device__ float2 g_PT [SS];       // phase_trig (amp * e^{i*phase})
__device__ float2 g_W  [NB*SS];    // packed input waves
__device__ float2 g_T1 [NB*SS];    // ping
__device__ float2 g_T2 [NB*SS];    // pong
__device__ float2 g_DaF[SS];       // D_a * F
__device__ float2 g_FDb[SS];       // F * D_b
__device__ float2 g_G1 [SS];       // (1/200) conj(F) D_a F
__device__ float2 g_G2 [SS];       // (1/200) F D_b conj(F)

// ---------------- shared-memory union (gemm tile vs phase scratch) ----------------
#define BM 64
#define BN 32
#define BK 16
#define APAD 66   // row stride of As in float2 (528B = 33*16B: float4-aligned, stores 2-way max)

struct SmemGemm {
    float2 As[BK][APAD];
    float2 Bs[BK][BN];
};
struct SmemPhase {
    float2 wm[8];
    unsigned long long top[4];   // [0]=top1 ch0, [1]=top1 ch1, [2]=top2 ch0, [3]=top2 ch1
    float e[256];
    int   res[2];
};
union SmemU {
    SmemGemm g;
    SmemPhase p;
};

// ---------------- threefry2x32 (host/reference version) ----------------
__host__ __device__ inline void tf2x32(uint32_t k0, uint32_t k1,
                                       uint32_t c0, uint32_t c1,
                                       uint32_t& o0, uint32_t& o1) {
    uint32_t ks2 = k0 ^ k1 ^ 0x1BD11BDAu;
    uint32_t x0 = c0 + k0, x1 = c1 + k1;
#define ROTL32(x,d) (((x)<<(d)) | ((x)>>(32-(d))))
#define RND(r) { x0 += x1; x1 = ROTL32(x1,(r)) ^ x0; }
    RND(13) RND(15) RND(26) RND(6)  x0 += k1;  x1 += ks2 + 1u;
    RND(17) RND(29) RND(16) RND(24) x0 += ks2; x1 += k0  + 2u;
    RND(13) RND(15) RND(26) RND(6)  x0 += k0;  x1 += k1  + 3u;
    RND(17) RND(29) RND(16) RND(24) x0 += k1;  x1 += ks2 + 4u;
    RND(13) RND(15) RND(26) RND(6)  x0 += ks2; x1 += k0  + 5u;
#undef RND
#undef ROTL32
    o0 = x0; o1 = x1;
}

// pipe-balanced add: a + b via IMAD (fma pipe); `one` is a runtime reg => ptxas keeps IMAD
__device__ __forceinline__ uint32_t madd(uint32_t a, uint32_t b, uint32_t one) {
    uint32_t r;
    asm("mad.lo.u32 %0, %1, %2, %3;" : "=r"(r) : "r"(a), "r"(one), "r"(b));
    return r;
}

// device threefry, counter (0, j), returns o0^o1 (partitionable 32-bit random_bits)
__device__ __forceinline__ uint32_t tf_bits(uint32_t k0, uint32_t k1, uint32_t j, uint32_t one) {
    uint32_t ks2 = k0 ^ k1 ^ 0x1BD11BDAu;
    uint32_t i1b = ks2 + 1u, i2b = k0 + 2u, i3b = k1 + 3u, i4b = ks2 + 4u, i5b = k0 + 5u;
    uint32_t x0 = k0;                 // c0 = 0
    uint32_t x1 = madd(j, k1, one);   // c1 = j
#define RNDM(r) { x0 = madd(x0, x1, one); x1 = __funnelshift_l(x1, x1, (r)) ^ x0; }
    RNDM(13) RNDM(15) RNDM(26) RNDM(6)
    x0 = madd(x0, k1,  one); x1 = madd(x1, i1b, one);
    RNDM(17) RNDM(29) RNDM(16) RNDM(24)
    x0 = madd(x0, ks2, one); x1 = madd(x1, i2b, one);
    RNDM(13) RNDM(15) RNDM(26) RNDM(6)
    x0 = madd(x0, k0,  one); x1 = madd(x1, i3b, one);
    RNDM(17) RNDM(29) RNDM(16) RNDM(24)
    x0 = madd(x0, k1,  one); x1 = madd(x1, i4b, one);
    RNDM(13) RNDM(15) RNDM(26) RNDM(6)
    x0 = madd(x0, ks2, one); x1 = madd(x1, i5b, one);
#undef RNDM
    return x0 ^ x1;
}

// bits -> uniform(1e-10, 1.0) exactly as jax._src.random._uniform (no FMA fusion!)
__device__ inline float uniform_from_bits(uint32_t bits) {
    float f = __uint_as_float((bits >> 9) | 0x3f800000u) - 1.0f;  // [0,1)
    float u = f + 1e-10f;
    return fmaxf(1e-10f, u);
}
__device__ inline float gumbel_precise(float u) { return -logf(-logf(u)); }

__device__ inline uint32_t ford(float z) {
    uint32_t b = __float_as_uint(z);
    return (b & 0x80000000u) ? ~b : (b | 0x80000000u);
}
__device__ inline float funord(uint32_t ob) {
    uint32_t b = (ob & 0x80000000u) ? (ob ^ 0x80000000u) : ~ob;
    return __uint_as_float(b);
}

// ---------------- fused preamble: twiddle + separable-h build + wave pack ----------------
__global__ void k_pre(const float* __restrict__ wr, const float* __restrict__ wi,
                      const float* __restrict__ hr, const float* __restrict__ hi) {
    int i = blockIdx.x * 256 + threadIdx.x;
    if (i < SS) {
        int j = i / S, k = i % S;
        int m = (j * k) % S;
        float sr, cr;
        sincospif((float)m / 100.0f, &sr, &cr);
        float2 F = make_float2(cr, -sr);
        g_F[i] = F;
        // a_j = h[j,0];  b_k = h[0,k] / h[0,0]
        float2 a = make_float2(hr[j * S], hi[j * S]);
        float2 h0k = make_float2(hr[k], hi[k]);
        float2 h00 = make_float2(hr[0], hi[0]);
        float inv = 1.0f / (h00.x * h00.x + h00.y * h00.y);
        float2 b = make_float2((h0k.x * h00.x + h0k.y * h00.y) * inv,
                               (h0k.y * h00.x - h0k.x * h00.y) * inv);
        g_DaF[i] = make_float2(a.x * F.x - a.y * F.y, a.x * F.y + a.y * F.x);
        g_FDb[i] = make_float2(F.x * b.x - F.y * b.y, F.x * b.y + F.y * b.x);
    }
    if (i < NB * SS) g_W[i] = make_float2(wr[i], wi[i]);
}

// ---------------- complex GEMM tile body (BM=64, BN=32, BK=16, 256 threads, 4x2 micro) ----------------
__device__ __forceinline__ void gemm_body(
    const float2* __restrict__ A, const float2* __restrict__ B, float2* __restrict__ C,
    int strideA, int strideB, int strideC,
    float cA, float cB, float scale,
    int bx, int by, int bz, SmemGemm& sm) {

    A += (size_t)bz * strideA;
    B += (size_t)bz * strideB;
    C += (size_t)bz * strideC;

    int tid = threadIdx.x;
    int tx = tid & 15;
    int ty = tid >> 4;
    int m0 = by * BM, n0 = bx * BN;

    float2 acc[4][2];
#pragma unroll
    for (int i = 0; i < 4; i++)
#pragma unroll
        for (int j = 0; j < 2; j++) acc[i][j] = make_float2(0.f, 0.f);

    for (int k0 = 0; k0 < S; k0 += BK) {
#pragma unroll
        for (int l = 0; l < 4; l++) {
            int e = tid + 256 * l;
            int m = e >> 4, kk = e & 15;
            float2 v = make_float2(0.f, 0.f);
            if (m0 + m < S && k0 + kk < S) v = A[(m0 + m) * S + (k0 + kk)];
            v.y *= cA;
            sm.As[kk][m] = v;
        }
#pragma unroll
        for (int l = 0; l < 2; l++) {
            int e = tid + 256 * l;
            int n = e & 31, kk = e >> 5;
            float2 v = make_float2(0.f, 0.f);
            if (k0 + kk < S && n0 + n < S) v = B[(k0 + kk) * S + (n0 + n)];
            v.y *= cB;
            sm.Bs[kk][n] = v;
        }
        __syncthreads();
#pragma unroll
        for (int kk = 0; kk < BK; kk++) {
            float4 bv  = *reinterpret_cast<const float4*>(&sm.Bs[kk][tx * 2]);
            float4 a01 = *reinterpret_cast<const float4*>(&sm.As[kk][ty * 4]);
            float4 a23 = *reinterpret_cast<const float4*>(&sm.As[kk][ty * 4 + 2]);
            float2 a[4] = { make_float2(a01.x, a01.y), make_float2(a01.z, a01.w),
                            make_float2(a23.x, a23.y), make_float2(a23.z, a23.w) };
            float2 bb[2] = { make_float2(bv.x, bv.y), make_float2(bv.z, bv.w) };
#pragma unroll
            for (int i = 0; i < 4; i++)
#pragma unroll
                for (int j = 0; j < 2; j++) {
                    acc[i][j].x = fmaf(a[i].x,  bb[j].x, acc[i][j].x);
                    acc[i][j].x = fmaf(-a[i].y, bb[j].y, acc[i][j].x);
                    acc[i][j].y = fmaf(a[i].x,  bb[j].y, acc[i][j].y);
                    acc[i][j].y = fmaf(a[i].y,  bb[j].x, acc[i][j].y);
                }
        }
        __syncthreads();
    }
#pragma unroll
    for (int i = 0; i < 4; i++) {
        int m = m0 + ty * 4 + i;
        if (m >= S) continue;
#pragma unroll
        for (int j = 0; j < 2; j++) {
            int n = n0 + tx * 2 + j;
            if (n >= S) continue;
            C[m * S + n] = make_float2(acc[i][j].x * scale, acc[i][j].y * scale);
        }
    }
}

// ---------------- G1/G2 builds: one launch, 56 blocks ----------------
__global__ void __launch_bounds__(256) k_gbuild() {
    __shared__ __align__(16) SmemU sm;
    int bid = blockIdx.x;
    if (bid < 28) {
        // G1 = (1/200) conj(F) @ (D_a F)
        gemm_body(g_F, g_DaF, g_G1, 0, 0, 0, -1.f, 1.f, 1.0f / 200.0f,
                  bid % 7, bid / 7, 0, sm.g);
    } else {
        // G2 = (1/200) (F D_b) @ conj(F)
        int lb = bid - 28;
        gemm_body(g_FDb, g_F, g_G2, 0, 0, 0, 1.f, -1.f, 1.0f / 200.0f,
                  lb % 7, lb / 7, 0, sm.g);
    }
}

// ---------------- phase body: u-domain screen + exact argmax ----------------
// screen: thread can win only if g(u) >= g(u_max) - 1 (since v in [0,1))  <=>  u >= u_max^e
__device__ __forceinline__ void phase_body(int pix,
        const float* __restrict__ volt, const float* __restrict__ pf, const float* __restrict__ itf,
        uint32_t k1a, uint32_t k1b, uint32_t k2a, uint32_t k2b, uint32_t one, SmemPhase& sm) {
    int p = threadIdx.x, warp = p >> 5, lane = p & 31;
    uint32_t j = (uint32_t)pix * 256u + (uint32_t)p;

    uint32_t bits0 = tf_bits(k1a, k1b, j, one);   // phase key
    uint32_t bits1 = tf_bits(k2a, k2b, j, one);   // intensity key
    float v  = volt[j];
    float u0 = uniform_from_bits(bits0);
    float u1 = uniform_from_bits(bits1);

    // block max of u per channel
    float m0 = u0, m1 = u1;
#pragma unroll
    for (int o = 16; o; o >>= 1) {
        m0 = fmaxf(m0, __shfl_xor_sync(0xffffffffu, m0, o));
        m1 = fmaxf(m1, __shfl_xor_sync(0xffffffffu, m1, o));
    }
    if (lane == 0) sm.wm[warp] = make_float2(m0, m1);
    if (p == 0) { sm.top[0] = 0ull; sm.top[1] = 0ull; sm.top[2] = 0ull; sm.top[3] = 0ull; }
    __syncthreads();
    float U0 = sm.wm[0].x, U1 = sm.wm[0].y;
#pragma unroll
    for (int w = 1; w < 8; w++) {
        U0 = fmaxf(U0, sm.wm[w].x);
        U1 = fmaxf(U1, sm.wm[w].y);
    }

    // conservative threshold u_max^e (0.999 guard keeps fast-math strictly below exact value)
    float t0 = __powf(U0, 2.7182818f) * 0.999f;
    float t1 = __powf(U1, 2.7182818f) * 0.999f;
    bool c0 = (u0 >= t0);
    bool c1 = (u1 >= t1);

    float z0 = 0.f, z1 = 0.f;
    unsigned long long key0 = 0ull, key1 = 0ull;
    if (c0) {
        z0 = (v + gumbel_precise(u0)) / 10.0f;     // exact score path (as XLA)
        key0 = ((unsigned long long)ford(z0) << 32) | (unsigned long long)(255 - p);
        atomicMax(&sm.top[0], key0);
    }
    if (c1) {
        z1 = (v + gumbel_precise(u1)) / 10.0f;
        key1 = ((unsigned long long)ford(z1) << 32) | (unsigned long long)(255 - p);
        atomicMax(&sm.top[1], key1);
    }
    __syncthreads();

    int i1c0 = 255 - (int)(sm.top[0] & 0xffull);
    int i1c1 = 255 - (int)(sm.top[1] & 0xffull);
    if (c0 && p != i1c0) atomicMax(&sm.top[2], key0);
    if (c1 && p != i1c1) atomicMax(&sm.top[3], key1);
    __syncthreads();

#pragma unroll
    for (int ch = 0; ch < 2; ch++) {
        unsigned long long K1 = sm.top[ch];
        unsigned long long K2 = sm.top[2 + ch];
        int   i1 = 255 - (int)(K1 & 0xffull);
        int   i2 = 255 - (int)(K2 & 0xffull);
        float zt1 = funord((uint32_t)(K1 >> 32));
        float zt2 = funord((uint32_t)(K2 >> 32));
        int result = i1;
        // rare danger branch: emulate reference softmax ulp-collapse (uniform across block)
        if (K2 != 0ull && i2 < i1 && (zt1 - zt2) < 1.5e-7f) {
            float uu = (ch == 0) ? u0 : u1;
            float zd = (v + gumbel_precise(uu)) / 10.0f;   // all-precise scores
            sm.e[p] = expf(zd - zt1);
            __syncthreads();
            for (int off = 128; off > 0; off >>= 1) {
                if (p < off) sm.e[p] += sm.e[p + off];
                __syncthreads();
            }
            float ssum = sm.e[0];
            float y1 = 1.0f / ssum;                 // exp(z1-z1)=1 exactly
            float y2 = expf(zt2 - zt1) / ssum;
            if (__float_as_uint(y1) == __float_as_uint(y2)) result = i2;
            __syncthreads();
        }
        if (p == 0) sm.res[ch] = result;
    }
    __syncthreads();

    if (p == 0) {
        float ph = pf[sm.res[0]];
        float am = itf[sm.res[1]] * 6.0f;
        float sn, cs;
        sincosf(ph, &sn, &cs);
        g_PT[pix] = make_float2(am * cs, am * sn);
    }
}

// ---------------- fused launch: gemm tiles (blocks < NGEMM) + phase pixels ----------------
__global__ void __launch_bounds__(256)
k_fused(int mode, int pixBase,
        const float* __restrict__ volt, const float* __restrict__ pf, const float* __restrict__ itf,
        uint32_t k1a, uint32_t k1b, uint32_t k2a, uint32_t k2b, uint32_t one) {
    __shared__ __align__(16) SmemU sm;
    int bid = blockIdx.x;
    if (bid < NGEMM) {
        int bz = bid / 28, rem = bid % 28;
        int by = rem / 7, bx = rem % 7;
        if (mode == 0) {
            // T1 = G1 @ W   (per batch)
            gemm_body(g_G1, g_W, g_T1, 0, SS, SS, 1.f, 1.f, 1.f, bx, by, bz, sm.g);
        } else {
            // T2 = T1 @ G2  (per batch)
            gemm_body(g_T1, g_G2, g_T2, SS, 0, SS, 1.f, 1.f, 1.f, bx, by, bz, sm.g);
        }
    } else {
        phase_body(pixBase + (bid - NGEMM), volt, pf, itf, k1a, k1b, k2a, k2b, one, sm.p);
    }
}

// ---------------- fused phase_trig multiply + pixel expansion ----------------
__global__ void k_expand(float* __restrict__ out) {
    int i = blockIdx.x, b = blockIdx.y;
    int tid = threadIdx.x;
    __shared__ float2 row[S];
    for (int j = tid; j < S; j += 256) {
        float2 v  = g_T2[b * SS + i * S + j];
        float2 pt = g_PT[i * S + j];
        row[j] = make_float2(v.x * pt.x - v.y * pt.y,
                             v.x * pt.y + v.y * pt.x);
    }
    __syncthreads();
    float4* obase = reinterpret_cast<float4*>(out) +
                    ((size_t)b * 2000 + (size_t)i * 10) * 1000;
    for (int di = 0; di < 10; di++) {
        float4* orow = obase + (size_t)di * 1000;
        if (di == 0 || di == 9) {
            for (int q = tid; q < 1000; q += 256) orow[q] = make_float4(0.f, 0.f, 0.f, 0.f);
        } else {
            for (int q = tid; q < 1000; q += 256) {
                int j  = q / 5;
                int k2 = q - j * 5;
                float2 v = row[j];
                float4 w;
                if      (k2 == 0) w = make_float4(0.f, 0.f, v.x, v.y);
                else if (k2 == 4) w = make_float4(v.x, v.y, 0.f, 0.f);
                else              w = make_float4(v.x, v.y, v.x, v.y);
                orow[q] = w;
            }
        }
    }
}

// ---------------- launch ----------------
extern "C" void kernel_launch(void* const* d_in, const int* in_sizes, int n_in,
                              void* d_out, int out_size) {
    const float* wr   = (const float*)d_in[0];
    const float* wi   = (const float*)d_in[1];
    const float* hr   = (const float*)d_in[2];
    const float* hi   = (const float*)d_in[3];
    const float* volt = (const float*)d_in[4];
    const float* pf   = (const float*)d_in[5];
    const float* itf  = (const float*)d_in[6];
    float* out = (float*)d_out;

    // jax.random.split(jax.random.key(42)), threefry_partitionable
    uint32_t k1a, k1b, k2a, k2b;
    tf2x32(0u, 42u, 0u, 0u, k1a, k1b);
    tf2x32(0u, 42u, 0u, 1u, k2a, k2b);

    k_pre<<<(NB * SS + 255) / 256, 256>>>(wr, wi, hr, hi);
    k_gbuild<<<56, 256>>>();

    // fused: GEMM pass 1 + phase pixels [0, 20000)
    k_fused<<<NGEMM + PHALF, 256>>>(0, 0,      volt, pf, itf, k1a, k1b, k2a, k2b, 1u);
    // fused: GEMM pass 2 + phase pixels [20000, 40000)
    k_fused<<<NGEMM + PHALF, 256>>>(1, PHALF,  volt, pf, itf, k1a, k1b, k2a, k2b, 1u);

    k_expand<<<dim3(S, NB), 256>>>(out);
}

// round 14
// speedup vs baseline: 1.9230x; 1.0547x over previous
#include <cuda_runtime.h>
#include <stdint.h>

#define S   200
#define SS  40000
#define NB  16
#define P   256
#define NGEMM 448          // 7 x 4 x 16 gemm tiles per pass

// ---------------- device scratch (no dynamic allocation allowed) ----------------
__device__ float2 g_F  [SS];       // DFT matrix exp(-2*pi*i*jk/200)
__device__ float2 g_PT [SS];       // phase_trig (amp * e^{i*phase})
__device__ float2 g_W  [NB*SS];    // packed input waves
__device__ float2 g_T1 [NB*SS];    // ping
__device__ float2 g_T2 [NB*SS];    // pong
__device__ float2 g_DaF[SS];       // D_a * F
__device__ float2 g_FDb[SS];       // F * D_b
__device__ float2 g_G1 [SS];       // (1/200) conj(F) D_a F
__device__ float2 g_G2 [SS];       // (1/200) F D_b conj(F)

// ---------------- gemm tile geometry ----------------
#define BM 64
#define BN 32
#define BK 16
#define APAD 66   // row stride of As in float2 (528B = 33*16B: float4-aligned, stores 2-way max)

struct SmemGemm {
    float2 As[BK][APAD];
    float2 Bs[BK][BN];
};

// ---------------- threefry2x32 (host/reference version) ----------------
__host__ __device__ inline void tf2x32(uint32_t k0, uint32_t k1,
                                       uint32_t c0, uint32_t c1,
                                       uint32_t& o0, uint32_t& o1) {
    uint32_t ks2 = k0 ^ k1 ^ 0x1BD11BDAu;
    uint32_t x0 = c0 + k0, x1 = c1 + k1;
#define ROTL32(x,d) (((x)<<(d)) | ((x)>>(32-(d))))
#define RND(r) { x0 += x1; x1 = ROTL32(x1,(r)) ^ x0; }
    RND(13) RND(15) RND(26) RND(6)  x0 += k1;  x1 += ks2 + 1u;
    RND(17) RND(29) RND(16) RND(24) x0 += ks2; x1 += k0  + 2u;
    RND(13) RND(15) RND(26) RND(6)  x0 += k0;  x1 += k1  + 3u;
    RND(17) RND(29) RND(16) RND(24) x0 += k1;  x1 += ks2 + 4u;
    RND(13) RND(15) RND(26) RND(6)  x0 += ks2; x1 += k0  + 5u;
#undef RND
#undef ROTL32
    o0 = x0; o1 = x1;
}

// pipe-balanced add: a + b via IMAD (fma pipe); `one` is a runtime reg => ptxas keeps IMAD
__device__ __forceinline__ uint32_t madd(uint32_t a, uint32_t b, uint32_t one) {
    uint32_t r;
    asm("mad.lo.u32 %0, %1, %2, %3;" : "=r"(r) : "r"(a), "r"(one), "r"(b));
    return r;
}

// device threefry, counter (0, j), returns o0^o1 (partitionable 32-bit random_bits)
__device__ __forceinline__ uint32_t tf_bits(uint32_t k0, uint32_t k1, uint32_t j, uint32_t one) {
    uint32_t ks2 = k0 ^ k1 ^ 0x1BD11BDAu;
    uint32_t i1b = ks2 + 1u, i2b = k0 + 2u, i3b = k1 + 3u, i4b = ks2 + 4u, i5b = k0 + 5u;
    uint32_t x0 = k0;                 // c0 = 0
    uint32_t x1 = madd(j, k1, one);   // c1 = j
#define RNDM(r) { x0 = madd(x0, x1, one); x1 = __funnelshift_l(x1, x1, (r)) ^ x0; }
    RNDM(13) RNDM(15) RNDM(26) RNDM(6)
    x0 = madd(x0, k1,  one); x1 = madd(x1, i1b, one);
    RNDM(17) RNDM(29) RNDM(16) RNDM(24)
    x0 = madd(x0, ks2, one); x1 = madd(x1, i2b, one);
    RNDM(13) RNDM(15) RNDM(26) RNDM(6)
    x0 = madd(x0, k0,  one); x1 = madd(x1, i3b, one);
    RNDM(17) RNDM(29) RNDM(16) RNDM(24)
    x0 = madd(x0, k1,  one); x1 = madd(x1, i4b, one);
    RNDM(13) RNDM(15) RNDM(26) RNDM(6)
    x0 = madd(x0, ks2, one); x1 = madd(x1, i5b, one);
#undef RNDM
    return x0 ^ x1;
}

// bits -> uniform(1e-10, 1.0) exactly as jax._src.random._uniform (no FMA fusion!)
__device__ inline float uniform_from_bits(uint32_t bits) {
    float f = __uint_as_float((bits >> 9) | 0x3f800000u) - 1.0f;  // [0,1)
    float u = f + 1e-10f;
    return fmaxf(1e-10f, u);
}
__device__ inline float gumbel_precise(float u) { return -logf(-logf(u)); }

__device__ inline uint32_t ford(float z) {
    uint32_t b = __float_as_uint(z);
    return (b & 0x80000000u) ? ~b : (b | 0x80000000u);
}
__device__ inline float funord(uint32_t ob) {
    uint32_t b = (ob & 0x80000000u) ? (ob ^ 0x80000000u) : ~ob;
    return __uint_as_float(b);
}

// ---------------- fused preamble: twiddle + separable-h build + wave pack ----------------
__global__ void k_pre(const float* __restrict__ wr, const float* __restrict__ wi,
                      const float* __restrict__ hr, const float* __restrict__ hi) {
    int i = blockIdx.x * 256 + threadIdx.x;
    if (i < SS) {
        int j = i / S, k = i % S;
        int m = (j * k) % S;
        float sr, cr;
        sincospif((float)m / 100.0f, &sr, &cr);
        float2 F = make_float2(cr, -sr);
        g_F[i] = F;
        // a_j = h[j,0];  b_k = h[0,k] / h[0,0]
        float2 a = make_float2(hr[j * S], hi[j * S]);
        float2 h0k = make_float2(hr[k], hi[k]);
        float2 h00 = make_float2(hr[0], hi[0]);
        float inv = 1.0f / (h00.x * h00.x + h00.y * h00.y);
        float2 b = make_float2((h0k.x * h00.x + h0k.y * h00.y) * inv,
                               (h0k.y * h00.x - h0k.x * h00.y) * inv);
        g_DaF[i] = make_float2(a.x * F.x - a.y * F.y, a.x * F.y + a.y * F.x);
        g_FDb[i] = make_float2(F.x * b.x - F.y * b.y, F.x * b.y + F.y * b.x);
    }
    if (i < NB * SS) g_W[i] = make_float2(wr[i], wi[i]);
}

// ---------------- complex GEMM tile body (BM=64, BN=32, BK=16, 256 threads, 4x2 micro) ----------------
__device__ __forceinline__ void gemm_body(
    const float2* __restrict__ A, const float2* __restrict__ B, float2* __restrict__ C,
    int strideA, int strideB, int strideC,
    float cA, float cB, float scale,
    int bx, int by, int bz, SmemGemm& sm) {

    A += (size_t)bz * strideA;
    B += (size_t)bz * strideB;
    C += (size_t)bz * strideC;

    int tid = threadIdx.x;
    int tx = tid & 15;
    int ty = tid >> 4;
    int m0 = by * BM, n0 = bx * BN;

    float2 acc[4][2];
#pragma unroll
    for (int i = 0; i < 4; i++)
#pragma unroll
        for (int j = 0; j < 2; j++) acc[i][j] = make_float2(0.f, 0.f);

    for (int k0 = 0; k0 < S; k0 += BK) {
#pragma unroll
        for (int l = 0; l < 4; l++) {
            int e = tid + 256 * l;
            int m = e >> 4, kk = e & 15;
            float2 v = make_float2(0.f, 0.f);
            if (m0 + m < S && k0 + kk < S) v = A[(m0 + m) * S + (k0 + kk)];
            v.y *= cA;
            sm.As[kk][m] = v;
        }
#pragma unroll
        for (int l = 0; l < 2; l++) {
            int e = tid + 256 * l;
            int n = e & 31, kk = e >> 5;
            float2 v = make_float2(0.f, 0.f);
            if (k0 + kk < S && n0 + n < S) v = B[(k0 + kk) * S + (n0 + n)];
            v.y *= cB;
            sm.Bs[kk][n] = v;
        }
        __syncthreads();
#pragma unroll
        for (int kk = 0; kk < BK; kk++) {
            float4 bv  = *reinterpret_cast<const float4*>(&sm.Bs[kk][tx * 2]);
            float4 a01 = *reinterpret_cast<const float4*>(&sm.As[kk][ty * 4]);
            float4 a23 = *reinterpret_cast<const float4*>(&sm.As[kk][ty * 4 + 2]);
            float2 a[4] = { make_float2(a01.x, a01.y), make_float2(a01.z, a01.w),
                            make_float2(a23.x, a23.y), make_float2(a23.z, a23.w) };
            float2 bb[2] = { make_float2(bv.x, bv.y), make_float2(bv.z, bv.w) };
#pragma unroll
            for (int i = 0; i < 4; i++)
#pragma unroll
                for (int j = 0; j < 2; j++) {
                    acc[i][j].x = fmaf(a[i].x,  bb[j].x, acc[i][j].x);
                    acc[i][j].x = fmaf(-a[i].y, bb[j].y, acc[i][j].x);
                    acc[i][j].y = fmaf(a[i].x,  bb[j].y, acc[i][j].y);
                    acc[i][j].y = fmaf(a[i].y,  bb[j].x, acc[i][j].y);
                }
        }
        __syncthreads();
    }
#pragma unroll
    for (int i = 0; i < 4; i++) {
        int m = m0 + ty * 4 + i;
        if (m >= S) continue;
#pragma unroll
        for (int j = 0; j < 2; j++) {
            int n = n0 + tx * 2 + j;
            if (n >= S) continue;
            C[m * S + n] = make_float2(acc[i][j].x * scale, acc[i][j].y * scale);
        }
    }
}

// ---------------- G1/G2 builds: one launch, 56 blocks ----------------
__global__ void __launch_bounds__(256) k_gbuild() {
    __shared__ __align__(16) SmemGemm sm;
    int bid = blockIdx.x;
    if (bid < 28) {
        // G1 = (1/200) conj(F) @ (D_a F)
        gemm_body(g_F, g_DaF, g_G1, 0, 0, 0, -1.f, 1.f, 1.0f / 200.0f,
                  bid % 7, bid / 7, 0, sm);
    } else {
        // G2 = (1/200) (F D_b) @ conj(F)
        int lb = bid - 28;
        gemm_body(g_FDb, g_F, g_G2, 0, 0, 0, 1.f, -1.f, 1.0f / 200.0f,
                  lb % 7, lb / 7, 0, sm);
    }
}

// ---------------- batch GEMM passes ----------------
__global__ void __launch_bounds__(256) k_gemm(int mode) {
    __shared__ __align__(16) SmemGemm sm;
    int bid = blockIdx.x;
    int bz = bid / 28, rem = bid % 28;
    int by = rem / 7, bx = rem % 7;
    if (mode == 0) {
        gemm_body(g_G1, g_W, g_T1, 0, SS, SS, 1.f, 1.f, 1.f, bx, by, bz, sm);   // T1 = G1 @ W
    } else {
        gemm_body(g_T1, g_G2, g_T2, SS, 0, SS, 1.f, 1.f, 1.f, bx, by, bz, sm);  // T2 = T1 @ G2
    }
}

// ---------------- standalone phase kernel (low regs, full occupancy) ----------------
// one block per pixel; u-domain screen: win requires g(u) >= g(u_max)-1  <=>  u >= u_max^e
__global__ void __launch_bounds__(256)
k_phase(const float* __restrict__ volt,
        const float* __restrict__ pf,
        const float* __restrict__ itf,
        uint32_t k1a, uint32_t k1b, uint32_t k2a, uint32_t k2b, uint32_t one) {
    __shared__ float2 s_wm[8];
    __shared__ unsigned long long s_top[4];
    __shared__ float s_e[256];
    __shared__ int   s_res[2];

    int pix = blockIdx.x;
    int p = threadIdx.x, warp = p >> 5, lane = p & 31;
    uint32_t j = (uint32_t)pix * 256u + (uint32_t)p;

    uint32_t bits0 = tf_bits(k1a, k1b, j, one);   // phase key
    uint32_t bits1 = tf_bits(k2a, k2b, j, one);   // intensity key
    float v  = volt[j];
    float u0 = uniform_from_bits(bits0);
    float u1 = uniform_from_bits(bits1);

    // block max of u per channel
    float m0 = u0, m1 = u1;
#pragma unroll
    for (int o = 16; o; o >>= 1) {
        m0 = fmaxf(m0, __shfl_xor_sync(0xffffffffu, m0, o));
        m1 = fmaxf(m1, __shfl_xor_sync(0xffffffffu, m1, o));
    }
    if (lane == 0) s_wm[warp] = make_float2(m0, m1);
    if (p == 0) { s_top[0] = 0ull; s_top[1] = 0ull; s_top[2] = 0ull; s_top[3] = 0ull; }
    __syncthreads();
    float U0 = s_wm[0].x, U1 = s_wm[0].y;
#pragma unroll
    for (int w = 1; w < 8; w++) {
        U0 = fmaxf(U0, s_wm[w].x);
        U1 = fmaxf(U1, s_wm[w].y);
    }

    // conservative threshold u_max^e (0.999 guard keeps fast-math strictly below exact value)
    float t0 = __powf(U0, 2.7182818f) * 0.999f;
    float t1 = __powf(U1, 2.7182818f) * 0.999f;
    bool c0 = (u0 >= t0);
    bool c1 = (u1 >= t1);

    float z0 = 0.f, z1 = 0.f;
    unsigned long long key0 = 0ull, key1 = 0ull;
    if (c0) {
        z0 = (v + gumbel_precise(u0)) / 10.0f;     // exact score path (as XLA)
        key0 = ((unsigned long long)ford(z0) << 32) | (unsigned long long)(255 - p);
        atomicMax(&s_top[0], key0);
    }
    if (c1) {
        z1 = (v + gumbel_precise(u1)) / 10.0f;
        key1 = ((unsigned long long)ford(z1) << 32) | (unsigned long long)(255 - p);
        atomicMax(&s_top[1], key1);
    }
    __syncthreads();

    int i1c0 = 255 - (int)(s_top[0] & 0xffull);
    int i1c1 = 255 - (int)(s_top[1] & 0xffull);
    if (c0 && p != i1c0) atomicMax(&s_top[2], key0);
    if (c1 && p != i1c1) atomicMax(&s_top[3], key1);
    __syncthreads();

#pragma unroll
    for (int ch = 0; ch < 2; ch++) {
        unsigned long long K1 = s_top[ch];
        unsigned long long K2 = s_top[2 + ch];
        int   i1 = 255 - (int)(K1 & 0xffull);
        int   i2 = 255 - (int)(K2 & 0xffull);
        float zt1 = funord((uint32_t)(K1 >> 32));
        float zt2 = funord((uint32_t)(K2 >> 32));
        int result = i1;
        // rare danger branch: emulate reference softmax ulp-collapse (uniform across block)
        if (K2 != 0ull && i2 < i1 && (zt1 - zt2) < 1.5e-7f) {
            float uu = (ch == 0) ? u0 : u1;
            float zd = (v + gumbel_precise(uu)) / 10.0f;   // all-precise scores
            s_e[p] = expf(zd - zt1);
            __syncthreads();
            for (int off = 128; off > 0; off >>= 1) {
                if (p < off) s_e[p] += s_e[p + off];
                __syncthreads();
            }
            float ssum = s_e[0];
            float y1 = 1.0f / ssum;                 // exp(z1-z1)=1 exactly
            float y2 = expf(zt2 - zt1) / ssum;
            if (__float_as_uint(y1) == __float_as_uint(y2)) result = i2;
            __syncthreads();
        }
        if (p == 0) s_res[ch] = result;
    }
    __syncthreads();

    if (p == 0) {
        float ph = pf[s_res[0]];
        float am = itf[s_res[1]] * 6.0f;
        float sn, cs;
        sincosf(ph, &sn, &cs);
        g_PT[pix] = make_float2(am * cs, am * sn);
    }
}

// ---------------- zero border rows of output (rows R with R%10 in {0,9}) ----------------
__global__ void k_zero(float* __restrict__ out) {
    int i = blockIdx.x, b = blockIdx.y;
    int tid = threadIdx.x;
    float4* base = reinterpret_cast<float4*>(out) +
                   ((size_t)b * 2000 + (size_t)i * 10) * 1000;
    float4 z = make_float4(0.f, 0.f, 0.f, 0.f);
    for (int q = tid; q < 1000; q += 256) {
        base[q] = z;               // row di=0
        base[9 * 1000 + q] = z;    // row di=9
    }
}

// ---------------- phase_trig multiply + interior-row pixel expansion ----------------
__global__ void k_expand(float* __restrict__ out) {
    int i = blockIdx.x, b = blockIdx.y;
    int tid = threadIdx.x;
    __shared__ float2 row[S];
    for (int j = tid; j < S; j += 256) {
        float2 v  = g_T2[b * SS + i * S + j];
        float2 pt = g_PT[i * S + j];
        row[j] = make_float2(v.x * pt.x - v.y * pt.y,
                             v.x * pt.y + v.y * pt.x);
    }
    __syncthreads();
    float4* obase = reinterpret_cast<float4*>(out) +
                    ((size_t)b * 2000 + (size_t)i * 10) * 1000;
    for (int di = 1; di < 9; di++) {           // border rows handled by k_zero
        float4* orow = obase + (size_t)di * 1000;
        for (int q = tid; q < 1000; q += 256) {
            int j  = q / 5;
            int k2 = q - j * 5;
            float2 v = row[j];
            float4 w;
            if      (k2 == 0) w = make_float4(0.f, 0.f, v.x, v.y);
            else if (k2 == 4) w = make_float4(v.x, v.y, 0.f, 0.f);
            else              w = make_float4(v.x, v.y, v.x, v.y);
            orow[q] = w;
        }
    }
}

// ---------------- launch: forked capture graph ----------------
extern "C" void kernel_launch(void* const* d_in, const int* in_sizes, int n_in,
                              void* d_out, int out_size) {
    const float* wr   = (const float*)d_in[0];
    const float* wi   = (const float*)d_in[1];
    const float* hr   = (const float*)d_in[2];
    const float* hi   = (const float*)d_in[3];
    const float* volt = (const float*)d_in[4];
    const float* pf   = (const float*)d_in[5];
    const float* itf  = (const float*)d_in[6];
    float* out = (float*)d_out;

    // streams/events created once on the (uncaptured) correctness call
    static cudaStream_t s1 = nullptr, s2 = nullptr;
    static cudaEvent_t  eFork, eJ1, eJ2;
    if (!s1) {
        cudaStreamCreateWithFlags(&s1, cudaStreamNonBlocking);
        cudaStreamCreateWithFlags(&s2, cudaStreamNonBlocking);
        cudaEventCreateWithFlags(&eFork, cudaEventDisableTiming);
        cudaEventCreateWithFlags(&eJ1,   cudaEventDisableTiming);
        cudaEventCreateWithFlags(&eJ2,   cudaEventDisableTiming);
    }

    // jax.random.split(jax.random.key(42)), threefry_partitionable
    uint32_t k1a, k1b, k2a, k2b;
    tf2x32(0u, 42u, 0u, 0u, k1a, k1b);
    tf2x32(0u, 42u, 0u, 1u, k2a, k2b);

    // fork: phase (s1) and border-zero (s2) are independent of the GEMM chain (s0)
    cudaEventRecord(eFork, 0);
    cudaStreamWaitEvent(s1, eFork, 0);
    cudaStreamWaitEvent(s2, eFork, 0);

    k_phase<<<SS, 256, 0, s1>>>(volt, pf, itf, k1a, k1b, k2a, k2b, 1u);
    cudaEventRecord(eJ1, s1);

    k_zero<<<dim3(S, NB), 256, 0, s2>>>(out);
    cudaEventRecord(eJ2, s2);

    // s0: preamble -> G builds -> two batch GEMM passes
    k_pre<<<(NB * SS + 255) / 256, 256>>>(wr, wi, hr, hi);
    k_gbuild<<<56, 256>>>();
    k_gemm<<<NGEMM, 256>>>(0);   // T1 = G1 @ W
    k_gemm<<<NGEMM, 256>>>(1);   // T2 = T1 @ G2

    // join and expand
    cudaStreamWaitEvent(0, eJ1, 0);
    cudaStreamWaitEvent(0, eJ2, 0);
    k_expand<<<dim3(S, NB), 256>>>(out);
}